// round 15
// baseline (speedup 1.0000x reference)
#include <cuda_runtime.h>
#include <cuda_fp16.h>
#include <cstdint>

// ---------------------------------------------------------------------------
// B=16, C=512, S=1024, HEAD=8, D_K=64
// heads view: token n -> channel n>>1, feature j=h*64+d -> spatial ((n&1)<<9)+j
// FP16 compensated selectively:
//   linear path (V-proj, P*V, both O-convs): A 2-term (Ah+Al)*Bh
//   softmax-dampened path (Q-proj, K-proj, S=Q*K): 1-term Ah*Bh
// cp.async 2-stage pipelines; ldmatrix (LDSM) fragment loads for K, V, GEMM-A;
// K tile XOR-swizzled; V pre-transposed (g_vpt); max-free softmax.
// ---------------------------------------------------------------------------
#define BATCH   16
#define CH      512
#define SP      1024
#define PER_B   (CH*SP)
#define WORDS_B (PER_B/2)

__device__ unsigned g_wwh[4*512*256], g_wwl[4*512*256];
__device__ unsigned g_xph[BATCH*WORDS_B];
__device__ unsigned g_qwh[BATCH*WORDS_B];
__device__ unsigned g_kwh[BATCH*WORDS_B];
__device__ unsigned g_vwh[BATCH*WORDS_B];
__device__ unsigned g_vpt[BATCH*WORDS_B];    // V transposed: [b][t16][j512][kp32]
__device__ unsigned g_aph[BATCH*WORDS_B];
__device__ float    g_o1[BATCH*PER_B];
__device__ unsigned g_oph[BATCH*WORDS_B];

__device__ __forceinline__ unsigned packh(float a, float b) {
    unsigned r;
    asm("cvt.rn.f16x2.f32 %0, %1, %2;" : "=r"(r) : "f"(b), "f"(a));
    return r;
}
__device__ __forceinline__ void split2h(float a, float b, unsigned& hi, unsigned& lo) {
    hi = packh(a, b);
    __half2 h = *reinterpret_cast<__half2*>(&hi);
    lo = packh(a - __half2float(__low2half(h)), b - __half2float(__high2half(h)));
}
__device__ __forceinline__ unsigned prmtb(unsigned a, unsigned b, unsigned sel) {
    unsigned d;
    asm("prmt.b32 %0,%1,%2,%3;" : "=r"(d) : "r"(a), "r"(b), "r"(sel));
    return d;
}
__device__ __forceinline__ float ex2(float x) {
    float y;
    asm("ex2.approx.f32 %0, %1;" : "=f"(y) : "f"(x));
    return y;
}
__device__ __forceinline__ void mma16(float* c, const unsigned* a, unsigned b0, unsigned b1) {
    asm volatile(
        "mma.sync.aligned.m16n8k16.row.col.f32.f16.f16.f32 "
        "{%0,%1,%2,%3},{%4,%5,%6,%7},{%8,%9},{%0,%1,%2,%3};"
        : "+f"(c[0]), "+f"(c[1]), "+f"(c[2]), "+f"(c[3])
        : "r"(a[0]), "r"(a[1]), "r"(a[2]), "r"(a[3]), "r"(b0), "r"(b1));
}
__device__ __forceinline__ void ldm4(unsigned& r0, unsigned& r1, unsigned& r2, unsigned& r3,
                                     uint32_t addr) {
    asm volatile("ldmatrix.sync.aligned.m8n8.x4.shared.b16 {%0,%1,%2,%3}, [%4];"
                 : "=r"(r0), "=r"(r1), "=r"(r2), "=r"(r3) : "r"(addr));
}
__device__ __forceinline__ void cpa16(uint32_t d, const void* s) {
    asm volatile("cp.async.cg.shared.global [%0], [%1], 16;" :: "r"(d), "l"(s));
}
#define CP_COMMIT() asm volatile("cp.async.commit_group;" ::: "memory")
#define CP_WAIT1()  asm volatile("cp.async.wait_group 1;" ::: "memory")
#define CP_WAIT0()  asm volatile("cp.async.wait_group 0;" ::: "memory")

// ------------------------------ prepasses ---------------------------------
__global__ __launch_bounds__(256)
void wsplit_kernel(const float* __restrict__ Wq, const float* __restrict__ Wk,
                   const float* __restrict__ Wv, const float* __restrict__ Wo)
{
    unsigned w = blockIdx.x * 256 + threadIdx.x;
    unsigned m = w >> 17, rem = w & 131071;
    const float* src = m == 0 ? Wq : (m == 1 ? Wk : (m == 2 ? Wv : Wo));
    float2 v = reinterpret_cast<const float2*>(src)[rem];
    unsigned h, l;
    split2h(v.x, v.y, h, l);
    g_wwh[w] = h; g_wwl[w] = l;
}

__global__ __launch_bounds__(256)
void xsplit_kernel(const float* __restrict__ X)
{
    unsigned f = blockIdx.x * 256 + threadIdx.x;
    unsigned b = f >> 16;
    unsigned kp = (f >> 8) & 255;
    unsigned n4 = (f & 255) << 2;
    const float* p = X + (size_t)b * PER_B + (size_t)(2 * kp) * SP + n4;
    float4 a = *reinterpret_cast<const float4*>(p);
    float4 c = *reinterpret_cast<const float4*>(p + SP);
    uint4 h;
    h.x = packh(a.x, c.x); h.y = packh(a.y, c.y);
    h.z = packh(a.z, c.z); h.w = packh(a.w, c.w);
    *reinterpret_cast<uint4*>(g_xph + (size_t)b * WORDS_B + (size_t)kp * 1024 + n4) = h;
}

// V transpose-pack: g_vpt[((b*16+t)*512 + h*64 + j2)*32 + kp]
//   = f16x2( V[key 2(32t+kp)][h*64+j2], V[key 2(32t+kp)+1][h*64+j2] )
// one block per (b,t,h): 32 channels x 64 spatial-words through smem
__global__ __launch_bounds__(256)
void vpackT_kernel()
{
    __shared__ unsigned sm[32][65];
    const unsigned bx = blockIdx.x;
    const unsigned b = bx >> 7, t = (bx >> 3) & 15, h = bx & 7;
    const int tid = threadIdx.x;
    const unsigned hoff2 = h * 32;
    // load: 512 uint4 (2048 words), coalesced
#pragma unroll
    for (int i = 0; i < 2; i++) {
        int idx = tid + i * 256;
        int kp = idx >> 4, u = idx & 15;
        unsigned w0 = (u < 8) ? (hoff2 + u * 4) : (256 + hoff2 + (u - 8) * 4);
        const unsigned* src = g_vwh + (size_t)b * WORDS_B + (size_t)(t * 32 + kp) * 512 + w0;
        uint4 v = *reinterpret_cast<const uint4*>(src);
        int c0 = (u < 8) ? u * 4 : 32 + (u - 8) * 4;
        sm[kp][c0] = v.x; sm[kp][c0 + 1] = v.y; sm[kp][c0 + 2] = v.z; sm[kp][c0 + 3] = v.w;
    }
    __syncthreads();
    // write: 2048 words, coalesced over kp
#pragma unroll
    for (int i = 0; i < 8; i++) {
        int idx = tid + i * 256;
        int j2 = idx >> 5, kp = idx & 31;
        unsigned a = sm[kp][j2 >> 1];
        unsigned c = sm[kp][32 + (j2 >> 1)];
        unsigned w = (j2 & 1) ? prmtb(a, c, 0x7632) : prmtb(a, c, 0x5410);
        g_vpt[((size_t)(b * 16 + t) * 512 + h * 64 + j2) * 32 + kp] = w;
    }
}

// ------------------------------ GEMM core ---------------------------------
// TERMS=2: acc += (Ah+Al)*Bh ; TERMS=1: acc += Ah*Bh.  A-frags via ldmatrix.
// smem words: Abuf0[0..5120) (Ah s20, Al +2560), Abuf1[5120..10240),
//             Bbuf0[10240..12416) stride136, Bbuf1[12416..14592)
#define GEMM_SMEM (14592*4)

template<int TERMS>
__device__ __forceinline__ void gemm_ld(uint32_t sb4, const unsigned* __restrict__ awh,
                                        const unsigned* __restrict__ awl,
                                        const unsigned* __restrict__ bph,
                                        int m0, int n0, int kp0, int bs, int tid)
{
    uint32_t abase = sb4 + bs * 5120 * 4;
#pragma unroll
    for (int i = 0; i < 2; i++) {
        int f = tid + i * 256;
        int r = f >> 2, seg = (f & 3) << 2;
        size_t src = (size_t)(m0 + r) * 256 + kp0 + seg;
        uint32_t d = abase + (r * 20 + seg) * 4;
        cpa16(d, awh + src);
        if (TERMS == 2) cpa16(d + 2560 * 4, awl + src);
    }
    uint32_t bbase = sb4 + (10240 + bs * 2176) * 4;
#pragma unroll
    for (int i = 0; i < 2; i++) {
        int f = tid + i * 256;
        int kp = f >> 5, seg = (f & 31) << 2;
        cpa16(bbase + (kp * 136 + seg) * 4,
              bph + (size_t)(kp0 + kp) * 1024 + n0 + seg);
    }
}

template<int TERMS>
__device__ __forceinline__ void gemm_acc(
    const unsigned* __restrict__ awh, const unsigned* __restrict__ awl,
    const unsigned* __restrict__ bph, int m0, int n0, unsigned* gsm, float acc[2][8][4])
{
    const int tid = threadIdx.x, lane = tid & 31, warp = tid >> 5;
    const int wm = warp & 3, wn = warp >> 2;
    const int g = lane >> 2, tg = lane & 3;
    const int r7 = lane & 7, mq = lane >> 3;        // ldmatrix lane roles
    uint32_t sb4 = (uint32_t)__cvta_generic_to_shared(gsm);

#pragma unroll
    for (int mt = 0; mt < 2; mt++)
#pragma unroll
        for (int nt = 0; nt < 8; nt++)
#pragma unroll
            for (int i = 0; i < 4; i++) acc[mt][nt][i] = 0.f;

    gemm_ld<TERMS>(sb4, awh, awl, bph, m0, n0, 0, 0, tid);
    CP_COMMIT();

    for (int c = 0; c < 16; c++) {
        const int bs = c & 1;
        if (c < 15) {
            gemm_ld<TERMS>(sb4, awh, awl, bph, m0, n0, (c + 1) * 16, (c + 1) & 1, tid);
            CP_COMMIT();
            CP_WAIT1();
        } else {
            CP_WAIT0();
        }
        __syncthreads();

        unsigned (*Bph)[136] = reinterpret_cast<unsigned(*)[136]>(gsm + 10240 + bs * 2176);
        const uint32_t abufb = sb4 + bs * 5120 * 4;

#pragma unroll
        for (int kc = 0; kc < 2; kc++) {
            const int base = kc * 8;
            unsigned ah[2][4], al[2][4];
#pragma unroll
            for (int mt = 0; mt < 2; mt++) {
                int rm = wm * 32 + mt * 16;
                // ldmatrix x4: m0 rows rm(+r) w base+0-3 -> a0; m1 rows rm+8 -> a1;
                //              m2 rows rm   w base+4-7 -> a2; m3 rows rm+8 -> a3
                uint32_t aaddr = abufb +
                    (((rm + ((mq & 1) << 3) + r7) * 20) + base + ((mq >> 1) << 2)) * 4;
                ldm4(ah[mt][0], ah[mt][1], ah[mt][2], ah[mt][3], aaddr);
                if (TERMS == 2)
                    ldm4(al[mt][0], al[mt][1], al[mt][2], al[mt][3], aaddr + 2560 * 4);
            }
#pragma unroll
            for (int ntc = 0; ntc < 2; ntc++) {
                unsigned bh0[4], bh1[4];
#pragma unroll
                for (int j = 0; j < 4; j++) {
                    int cn = wn * 64 + (ntc * 4 + j) * 8;
                    bh0[j] = Bph[base + tg][cn + g];
                    bh1[j] = Bph[base + tg + 4][cn + g];
                }
#pragma unroll
                for (int j = 0; j < 4; j++) {
                    mma16(acc[0][ntc * 4 + j], ah[0], bh0[j], bh1[j]);
                    mma16(acc[1][ntc * 4 + j], ah[1], bh0[j], bh1[j]);
                }
                if (TERMS == 2) {
#pragma unroll
                    for (int j = 0; j < 4; j++) {
                        mma16(acc[0][ntc * 4 + j], al[0], bh0[j], bh1[j]);
                        mma16(acc[1][ntc * 4 + j], al[1], bh0[j], bh1[j]);
                    }
                }
            }
        }
        __syncthreads();
    }
}

// fused QKV: grid (8, 12, 16); y>>2 selects {Q,K,V}; Q/K 1-term, V 2-term
__global__ __launch_bounds__(256, 2)
void qkv_kernel(const float* __restrict__ bq, const float* __restrict__ bk,
                const float* __restrict__ bv)
{
    extern __shared__ unsigned gsm[];
    const int sel = blockIdx.y >> 2;
    const int m0 = (blockIdx.y & 3) * 128;
    const int n0 = blockIdx.x * 128;
    const int b  = blockIdx.z;
    const unsigned* awh = g_wwh + sel * 131072;
    const unsigned* awl = g_wwl + sel * 131072;
    const unsigned* bph = g_xph + (size_t)b * WORDS_B;
    const float* bias = sel == 0 ? bq : (sel == 1 ? bk : bv);
    unsigned* oh = (sel == 0 ? g_qwh : (sel == 1 ? g_kwh : g_vwh)) + (size_t)b * WORDS_B;

    float acc[2][8][4];
    if (sel == 2) gemm_acc<2>(awh, awl, bph, m0, n0, gsm, acc);
    else          gemm_acc<1>(awh, awl, bph, m0, n0, gsm, acc);

    const int tid = threadIdx.x, lane = tid & 31, warp = tid >> 5;
    const int wm = warp & 3, wn = warp >> 2;
    const int g = lane >> 2, tg = lane & 3;
#pragma unroll
    for (int mt = 0; mt < 2; mt++) {
        int r0 = m0 + wm * 32 + mt * 16 + g;
        float bi0 = bias[r0], bi1 = bias[r0 + 8];
#pragma unroll
        for (int nt = 0; nt < 8; nt++) {
            int cn = n0 + wn * 64 + nt * 8 + 2 * tg;
            oh[(size_t)r0 * 512 + (cn >> 1)] =
                packh(acc[mt][nt][0] + bi0, acc[mt][nt][1] + bi0);
            oh[(size_t)(r0 + 8) * 512 + (cn >> 1)] =
                packh(acc[mt][nt][2] + bi1, acc[mt][nt][3] + bi1);
        }
    }
}

// O-conv GEMM: A = Wo hi/lo (2-term), B = pair-packed hi; float out
__global__ __launch_bounds__(256, 2)
void gemm_f_kernel(const float* __restrict__ bias,
                   const unsigned* __restrict__ bph_all, float* __restrict__ Y)
{
    extern __shared__ unsigned gsm[];
    const int m0 = blockIdx.y * 128, n0 = blockIdx.x * 128, b = blockIdx.z;
    const unsigned* bph = bph_all + (size_t)b * WORDS_B;
    float* Yb = Y + (size_t)b * PER_B;

    float acc[2][8][4];
    gemm_acc<2>(g_wwh + 3 * 131072, g_wwl + 3 * 131072, bph, m0, n0, gsm, acc);

    const int tid = threadIdx.x, lane = tid & 31, warp = tid >> 5;
    const int wm = warp & 3, wn = warp >> 2;
    const int g = lane >> 2, tg = lane & 3;
#pragma unroll
    for (int mt = 0; mt < 2; mt++) {
        int r0 = m0 + wm * 32 + mt * 16 + g;
        float bi0 = bias[r0], bi1 = bias[r0 + 8];
#pragma unroll
        for (int nt = 0; nt < 8; nt++) {
            int cn = n0 + wn * 64 + nt * 8 + 2 * tg;
            Yb[(size_t)r0 * SP + cn]           = acc[mt][nt][0] + bi0;
            Yb[(size_t)r0 * SP + cn + 1]       = acc[mt][nt][1] + bi0;
            Yb[(size_t)(r0 + 8) * SP + cn]     = acc[mt][nt][2] + bi1;
            Yb[(size_t)(r0 + 8) * SP + cn + 1] = acc[mt][nt][3] + bi1;
        }
    }
}

// ------------------------------ attention ---------------------------------
// grid (8 qblocks of 128 rows, 8 heads, 16 b), 256 thr, 2 CTAs/SM.
// S = Qh*Kh (1-term, LDSM K); P*V 2-term (LDSM V). 16 key-tiles of 64.
// smem words: Kbuf 2x[64][32] swizzled [0..4096), VhT 2x[64][36] [4096..8704)
// epilogue Os float[128][68] = 8704 w reuses [0..8704)
#define ATTN_SMEM (8704*4)

__device__ __forceinline__ size_t tok_off(int n, int hoff) {
    return (size_t)(n >> 1) * SP + ((n & 1) << 9) + hoff;
}

__device__ __forceinline__ void attn_ld(uint32_t sb4, size_t bbw, int b, int hoff,
                                        int t, int tid)
{
    const int bs = t & 1;
#pragma unroll
    for (int i = 0; i < 2; i++) {
        int f = tid + i * 256;
        int r = f >> 3, q4 = (f & 7) << 2;
        size_t kw = bbw + (tok_off(t * 64 + r, hoff) >> 1) + q4;
        uint32_t c = q4 ^ ((r & 7) << 2);
        cpa16(sb4 + (bs * 2048 + r * 32 + c) * 4, g_kwh + kw);
    }
    // VhT tile: 64 rows (j within head) x 32 kp, stride 36
    const unsigned* vsrc = g_vpt + ((size_t)(b * 16 + t) * 512 + hoff) * 32;
#pragma unroll
    for (int i = 0; i < 2; i++) {
        int f = tid + i * 256;
        int r = f >> 3, q4 = (f & 7) << 2;
        cpa16(sb4 + (4096 + bs * 2304 + r * 36 + q4) * 4, vsrc + r * 32 + q4);
    }
}

__global__ __launch_bounds__(256, 2)
void attn_kernel()
{
    extern __shared__ unsigned smem_u[];
    uint32_t sb4 = (uint32_t)__cvta_generic_to_shared(smem_u);

    const int tid = threadIdx.x, lane = tid & 31, warp = tid >> 5;
    const int g = lane >> 2, tg = lane & 3;
    const int r7 = lane & 7, mq = lane >> 3;

    const int b = blockIdx.z, h = blockIdx.y;
    const int n0 = blockIdx.x * 128;
    const size_t bbw = (size_t)b * WORDS_B;
    const int hoff = h * 64;

    // ldmatrix per-lane offsets
    const unsigned kswz = r7 << 2;
    const unsigned koff0 = ((mq << 2) ^ kswz);            // kc 0,1
    const unsigned koff1 = ((16 + (mq << 2)) ^ kswz);     // kc 2,3

    // Q fragments, hi only (S errors softmax-dampened)
    const int r0l = warp * 16 + g, r1l = r0l + 8;
    const size_t w0 = bbw + (tok_off(n0 + r0l, hoff) >> 1);
    const size_t w1 = bbw + (tok_off(n0 + r1l, hoff) >> 1);
    unsigned qh[4][4];
#pragma unroll
    for (int kc = 0; kc < 4; kc++) {
        qh[kc][0] = g_qwh[w0 + kc * 8 + tg];
        qh[kc][1] = g_qwh[w1 + kc * 8 + tg];
        qh[kc][2] = g_qwh[w0 + kc * 8 + tg + 4];
        qh[kc][3] = g_qwh[w1 + kc * 8 + tg + 4];
    }

    float l0 = 0.f, l1 = 0.f;
    float oa[8][4];
#pragma unroll
    for (int dt = 0; dt < 8; dt++)
#pragma unroll
        for (int i = 0; i < 4; i++) oa[dt][i] = 0.f;

    attn_ld(sb4, bbw, b, hoff, 0, tid);
    CP_COMMIT();

    const float C = 0.18033688011f;              // 0.125 * log2(e)

    for (int t = 0; t < 16; t++) {
        const int bs = t & 1;
        if (t < 15) {
            attn_ld(sb4, bbw, b, hoff, t + 1, tid);
            CP_COMMIT();
            CP_WAIT1();
        } else {
            CP_WAIT0();
        }
        __syncthreads();

        const uint32_t kbase = sb4 + (bs * 2048) * 4;
        const uint32_t vbase = sb4 + (4096 + bs * 2304) * 4;

        // S = Qh Kh^T via LDSM: per j, x4 gives (b0,b1) for kc and kc+1
        float sc[8][4];
#pragma unroll
        for (int nt = 0; nt < 8; nt++) {
            sc[nt][0] = sc[nt][1] = sc[nt][2] = sc[nt][3] = 0.f;
        }
#pragma unroll
        for (int j = 0; j < 8; j++) {
            unsigned k0, k1, k2, k3;
            ldm4(k0, k1, k2, k3, kbase + ((j * 8 + r7) * 32 + koff0) * 4);
            mma16(sc[j], qh[0], k0, k1);
            mma16(sc[j], qh[1], k2, k3);
        }
#pragma unroll
        for (int j = 0; j < 8; j++) {
            unsigned k0, k1, k2, k3;
            ldm4(k0, k1, k2, k3, kbase + ((j * 8 + r7) * 32 + koff1) * 4);
            mma16(sc[j], qh[2], k0, k1);
            mma16(sc[j], qh[3], k2, k3);
        }

        // direct exp2 (max-free)
        float ps0 = 0.f, ps1 = 0.f;
#pragma unroll
        for (int nt = 0; nt < 8; nt++) {
            sc[nt][0] = ex2(sc[nt][0] * C);
            sc[nt][1] = ex2(sc[nt][1] * C);
            sc[nt][2] = ex2(sc[nt][2] * C);
            sc[nt][3] = ex2(sc[nt][3] * C);
            ps0 += sc[nt][0] + sc[nt][1];
            ps1 += sc[nt][2] + sc[nt][3];
        }
        ps0 += __shfl_xor_sync(0xffffffff, ps0, 1);
        ps0 += __shfl_xor_sync(0xffffffff, ps0, 2);
        ps1 += __shfl_xor_sync(0xffffffff, ps1, 1);
        ps1 += __shfl_xor_sync(0xffffffff, ps1, 2);
        l0 += ps0;
        l1 += ps1;

        // O += P V (P split hi/lo); LDSM V: x4 = (b0,b1 for dt, dt+1)
#pragma unroll
        for (int nt2 = 0; nt2 < 4; nt2++) {
            const float* s0 = sc[2 * nt2];
            const float* s1 = sc[2 * nt2 + 1];
            unsigned pah[4], pal[4];
            split2h(s0[0], s0[1], pah[0], pal[0]);
            split2h(s0[2], s0[3], pah[1], pal[1]);
            split2h(s1[0], s1[1], pah[2], pal[2]);
            split2h(s1[2], s1[3], pah[3], pal[3]);
            const unsigned vword = nt2 * 8 + ((mq & 1) << 2);
#pragma unroll
            for (int dt = 0; dt < 8; dt += 2) {
                unsigned v0, v1, v2, v3;
                // rows (dt + (mq>>1))*8 + r7, word nt2*8 + (mq&1)*4
                ldm4(v0, v1, v2, v3,
                     vbase + (((dt + (mq >> 1)) * 8 + r7) * 36 + vword) * 4);
                mma16(oa[dt],     pah, v0, v1);
                mma16(oa[dt + 1], pah, v2, v3);
                mma16(oa[dt],     pal, v0, v1);
                mma16(oa[dt + 1], pal, v2, v3);
            }
        }
        __syncthreads();
    }

    const float inv0 = 1.f / l0, inv1 = 1.f / l1;

    float (*Os)[68] = reinterpret_cast<float(*)[68]>(smem_u);
#pragma unroll
    for (int dt = 0; dt < 8; dt++) {
        Os[r0l][dt * 8 + 2 * tg]     = oa[dt][0] * inv0;
        Os[r0l][dt * 8 + 2 * tg + 1] = oa[dt][1] * inv0;
        Os[r1l][dt * 8 + 2 * tg]     = oa[dt][2] * inv1;
        Os[r1l][dt * 8 + 2 * tg + 1] = oa[dt][3] * inv1;
    }
    __syncthreads();
#pragma unroll
    for (int it = 0; it < 16; it++) {
        int f = tid + it * 256;
        int jp = f >> 7, nl = f & 127;
        g_aph[bbw + (size_t)((hoff >> 1) + jp) * 1024 + n0 + nl]
            = packh(Os[nl][2 * jp], Os[nl][2 * jp + 1]);
    }
}

// --------------------- InstanceNorm (channel pair) ------------------------
__global__ __launch_bounds__(256)
void inorm2_kernel()
{
    __shared__ float ss[8], sq[8], stats[4];
    __shared__ float sbuf[2][1024];
    const float* p = g_o1 + (size_t)blockIdx.x * 2048;
    const int tid = threadIdx.x, lane = tid & 31, warp = tid >> 5;
    const int ch = tid >> 7, i2 = tid & 127;
    const float* row = p + ch * 1024;
    float4 a = reinterpret_cast<const float4*>(row)[i2 * 2];
    float4 c = reinterpret_cast<const float4*>(row)[i2 * 2 + 1];
    float s = a.x + a.y + a.z + a.w + c.x + c.y + c.z + c.w;
    float q = a.x * a.x + a.y * a.y + a.z * a.z + a.w * a.w
            + c.x * c.x + c.y * c.y + c.z * c.z + c.w * c.w;
#pragma unroll
    for (int off = 16; off > 0; off >>= 1) {
        s += __shfl_xor_sync(0xffffffff, s, off);
        q += __shfl_xor_sync(0xffffffff, q, off);
    }
    if (lane == 0) { ss[warp] = s; sq[warp] = q; }
    __syncthreads();
    if (tid == 0 || tid == 128) {
        int base = ch * 4;
        float S = ss[base] + ss[base + 1] + ss[base + 2] + ss[base + 3];
        float Qs = sq[base] + sq[base + 1] + sq[base + 2] + sq[base + 3];
        float mean = S * (1.f / SP);
        float var = Qs * (1.f / SP) - mean * mean;
        stats[ch * 2] = mean;
        stats[ch * 2 + 1] = rsqrtf(var + 1e-5f);
    }
    __syncthreads();
    float mean = stats[ch * 2], inv = stats[ch * 2 + 1];
    float* dst = &sbuf[ch][i2 * 8];
    dst[0] = (a.x - mean) * inv; dst[1] = (a.y - mean) * inv;
    dst[2] = (a.z - mean) * inv; dst[3] = (a.w - mean) * inv;
    dst[4] = (c.x - mean) * inv; dst[5] = (c.y - mean) * inv;
    dst[6] = (c.z - mean) * inv; dst[7] = (c.w - mean) * inv;
    __syncthreads();
#pragma unroll
    for (int it = 0; it < 4; it++) {
        int sidx = tid + it * 256;
        g_oph[(size_t)blockIdx.x * 1024 + sidx] = packh(sbuf[0][sidx], sbuf[1][sidx]);
    }
}

// ---------------------------------------------------------------------------
extern "C" void kernel_launch(void* const* d_in, const int* in_sizes, int n_in,
                              void* d_out, int out_size)
{
    const float* x  = (const float*)d_in[0];
    const float* Wq = (const float*)d_in[1];
    const float* bq = (const float*)d_in[2];
    const float* Wk = (const float*)d_in[3];
    const float* bk = (const float*)d_in[4];
    const float* Wv = (const float*)d_in[5];
    const float* bv = (const float*)d_in[6];
    const float* Wo = (const float*)d_in[7];
    const float* bo = (const float*)d_in[8];

    unsigned *aph, *oph;
    float *o1;
    cudaGetSymbolAddress((void**)&aph, g_aph);
    cudaGetSymbolAddress((void**)&oph, g_oph);
    cudaGetSymbolAddress((void**)&o1,  g_o1);

    cudaFuncSetAttribute(qkv_kernel,    cudaFuncAttributeMaxDynamicSharedMemorySize, GEMM_SMEM);
    cudaFuncSetAttribute(gemm_f_kernel, cudaFuncAttributeMaxDynamicSharedMemorySize, GEMM_SMEM);
    cudaFuncSetAttribute(attn_kernel,   cudaFuncAttributeMaxDynamicSharedMemorySize, ATTN_SMEM);

    wsplit_kernel<<<2048, 256>>>(Wq, Wk, Wv, Wo);
    xsplit_kernel<<<4096, 256>>>(x);

    qkv_kernel<<<dim3(8, 12, BATCH), 256, GEMM_SMEM>>>(bq, bk, bv);
    vpackT_kernel<<<2048, 256>>>();

    attn_kernel<<<dim3(8, 8, BATCH), 256, ATTN_SMEM>>>();

    gemm_f_kernel<<<dim3(8, 4, BATCH), 256, GEMM_SMEM>>>(bo, aph, o1);
    inorm2_kernel<<<BATCH * 256, 256>>>();
    gemm_f_kernel<<<dim3(8, 4, BATCH), 256, GEMM_SMEM>>>(bo, oph, (float*)d_out);
}